// round 7
// baseline (speedup 1.0000x reference)
#include <cuda_runtime.h>
#include <cuda_fp16.h>

// ---------------- problem constants ----------------
#define BATCH    8192
#define IN_FEAT  512
#define OUT_FEAT 512
#define GK       13                       // GRID_SIZE + K
#define KTOT     (IN_FEAT + IN_FEAT*GK)   // 7168
#define ROWBYTES (KTOT * 2)               // 14336 bytes per fp16 row
#define KCHUNK   64                       // fp16 elems per stage chunk = 128B
#define NCHUNKS  (KTOT / KCHUNK)          // 112
#define TILE_M   128
#define TILE_N   128

// ---------------- scratch (device globals; no allocation allowed) ------
__device__ __half g_act[(size_t)BATCH * KTOT];     // 117 MB activation matrix
__device__ __half g_wk [(size_t)OUT_FEAT * KTOT];  // 7.3 MB packed weights

// ---------------- helpers ----------------
__device__ __forceinline__ unsigned smem_u32(const void* p) {
    unsigned a;
    asm("{ .reg .u64 t; cvta.to.shared.u64 t, %1; cvt.u32.u64 %0, t; }"
        : "=r"(a) : "l"(p));
    return a;
}
__device__ __forceinline__ void cp16(unsigned saddr, const void* gaddr) {
    asm volatile("cp.async.cg.shared.global [%0], [%1], 16;"
                 :: "r"(saddr), "l"(gaddr));
}
__device__ __forceinline__ void cp_commit() {
    asm volatile("cp.async.commit_group;");
}
__device__ __forceinline__ void cp_wait1() {
    asm volatile("cp.async.wait_group 1;");
}
__device__ __forceinline__ void cp_wait0() {
    asm volatile("cp.async.wait_group 0;");
}
__device__ __forceinline__ void ldx4(unsigned* r, unsigned addr) {
    asm volatile("ldmatrix.sync.aligned.m8n8.x4.shared.b16 {%0,%1,%2,%3}, [%4];"
                 : "=r"(r[0]), "=r"(r[1]), "=r"(r[2]), "=r"(r[3]) : "r"(addr));
}
__device__ __forceinline__ void mma16816(float* d, const unsigned* a,
                                         unsigned b0, unsigned b1) {
    asm volatile(
        "mma.sync.aligned.m16n8k16.row.col.f32.f16.f16.f32 "
        "{%0,%1,%2,%3}, {%4,%5,%6,%7}, {%8,%9}, {%0,%1,%2,%3};"
        : "+f"(d[0]), "+f"(d[1]), "+f"(d[2]), "+f"(d[3])
        : "r"(a[0]), "r"(a[1]), "r"(a[2]), "r"(a[3]), "r"(b0), "r"(b1));
}

// ================= kernel 0: pack weights -> fp16 =================
__global__ void kan_wprep(const float* __restrict__ base_w,
                          const float* __restrict__ spline_w) {
    size_t idx = (size_t)blockIdx.x * blockDim.x + threadIdx.x;
    if (idx >= (size_t)OUT_FEAT * KTOT) return;
    int o = (int)(idx / KTOT);
    int k = (int)(idx % KTOT);
    float v = (k < IN_FEAT)
        ? base_w[(size_t)o * IN_FEAT + k]
        : spline_w[(size_t)o * (IN_FEAT * GK) + (k - IN_FEAT)];
    g_wk[idx] = __float2half_rn(v);
}

// ===== kernel 1: activations = [silu(x) | uniform cubic B-spline bases] =====
// knots t_j = -3.2 + 0.4 j (j = 0..16); closed-form cubic B-spline weights.
__global__ void kan_act(const float* __restrict__ x) {
    size_t idx = (size_t)blockIdx.x * blockDim.x + threadIdx.x;
    if (idx >= (size_t)BATCH * IN_FEAT) return;
    int b = (int)(idx / IN_FEAT);
    int i = (int)(idx % IN_FEAT);
    float xv = x[idx];

    __half* row = g_act + (size_t)b * KTOT;
    row[i] = __float2half_rn(xv / (1.0f + __expf(-xv)));   // silu branch

    float t = (xv + 3.2f) * 2.5f;
    float w0 = 0.f, w1 = 0.f, w2 = 0.f, w3 = 0.f;
    int g0 = -100;                                         // out of range -> zeros
    if (t >= 0.0f && t < 16.0f) {
        int j = (int)t;
        float u  = t - (float)j;
        float um = 1.0f - u;
        float u2 = u * u, u3 = u2 * u;
        float um3 = um * um * um;
        const float c6 = 1.0f / 6.0f;
        w0 = um3 * c6;                                        // basis j-3
        w1 = (3.0f * u3 - 6.0f * u2 + 4.0f) * c6;             // basis j-2
        w2 = (-3.0f * u3 + 3.0f * u2 + 3.0f * u + 1.0f) * c6; // basis j-1
        w3 = u3 * c6;                                         // basis j
        g0 = j - 3;
    }
    __half* sp = row + IN_FEAT + (size_t)i * GK;
#pragma unroll
    for (int g = 0; g < GK; ++g) {
        int m = g - g0;
        float v = (m == 0) ? w0 : (m == 1) ? w1 : (m == 2) ? w2 : (m == 3) ? w3 : 0.0f;
        sp[g] = __float2half_rn(v);
    }
}

// ================= kernel 2: fp16 mma.sync GEMM + bias =================
// C[8192,512] = Act[8192,7168] * Wk[512,7168]^T + bias
#define A_BYTES     (TILE_M * KCHUNK * 2)        // 16384
#define B_BYTES     (TILE_N * KCHUNK * 2)        // 16384
#define STAGE_BYTES (A_BYTES + B_BYTES)          // 32768
#define SMEM_TOTAL  (2 * STAGE_BYTES)            // 65536

__global__ void __launch_bounds__(256, 2)
kan_gemm(const float* __restrict__ bias, float* __restrict__ out) {
    extern __shared__ char smem[];
    unsigned sb = smem_u32(smem);
    int tid  = threadIdx.x;
    int w    = tid >> 5;
    int lane = tid & 31;
    int wm   = w >> 2;          // 0..1  (M direction, 64 rows each)
    int wn   = w & 3;           // 0..3  (N direction, 32 cols each)

    int m_base = (blockIdx.x >> 2) * TILE_M;
    int n_base = (blockIdx.x & 3) * TILE_N;

    // ---- cp.async loader precompute: 4 groups of 16B per thread per tile ----
    unsigned so[4];
    const char* ga[4];
    const char* gb[4];
#pragma unroll
    for (int q = 0; q < 4; ++q) {
        int g   = tid + q * 256;          // 0..1023
        int row = g >> 3;                 // 0..127
        int c8  = g & 7;                  // 16B column
        so[q] = (unsigned)((row << 7) + (((unsigned)c8 ^ (row & 7)) << 4));
        ga[q] = (const char*)g_act + (size_t)(m_base + row) * ROWBYTES + c8 * 16;
        gb[q] = (const char*)g_wk  + (size_t)(n_base + row) * ROWBYTES + c8 * 16;
    }

    // ---- ldmatrix per-lane precompute ----
    int lrow = lane & 15;
    unsigned lh = (unsigned)(lane >> 4);
    unsigned arow[4], abit[4];
#pragma unroll
    for (int mt = 0; mt < 4; ++mt) {
        int r = wm * 64 + mt * 16 + lrow;
        arow[mt] = (unsigned)(r << 7);
        abit[mt] = (unsigned)(r & 7);
    }
    unsigned brow[2], bbit[2];
#pragma unroll
    for (int bt = 0; bt < 2; ++bt) {
        int r = wn * 32 + bt * 16 + lrow;
        brow[bt] = (unsigned)(r << 7);
        bbit[bt] = (unsigned)(r & 7);
    }

    float acc[4][4][4];
#pragma unroll
    for (int mt = 0; mt < 4; ++mt)
#pragma unroll
        for (int nt = 0; nt < 4; ++nt)
#pragma unroll
            for (int e = 0; e < 4; ++e) acc[mt][nt][e] = 0.0f;

    // ---- prologue: load chunk 0 into stage 0 ----
    {
        unsigned base = sb;
#pragma unroll
        for (int q = 0; q < 4; ++q) cp16(base + so[q], ga[q]);
#pragma unroll
        for (int q = 0; q < 4; ++q) cp16(base + A_BYTES + so[q], gb[q]);
        cp_commit();
    }

    for (int c = 0; c < NCHUNKS; ++c) {
        if (c + 1 < NCHUNKS) {
            unsigned base = sb + ((c + 1) & 1) * STAGE_BYTES;
            size_t koff = (size_t)(c + 1) * 128;
#pragma unroll
            for (int q = 0; q < 4; ++q) cp16(base + so[q], ga[q] + koff);
#pragma unroll
            for (int q = 0; q < 4; ++q) cp16(base + A_BYTES + so[q], gb[q] + koff);
            cp_commit();
            cp_wait1();
        } else {
            cp_wait0();
        }
        __syncthreads();

        unsigned Ab = sb + (c & 1) * STAGE_BYTES;
        unsigned Bb = Ab + A_BYTES;

#pragma unroll
        for (int kt = 0; kt < 4; ++kt) {
            unsigned c8 = (unsigned)(kt * 2) + lh;
            unsigned af[4][4];
#pragma unroll
            for (int mt = 0; mt < 4; ++mt)
                ldx4(af[mt], Ab + arow[mt] + ((c8 ^ abit[mt]) << 4));
            unsigned bf[2][4];
#pragma unroll
            for (int bt = 0; bt < 2; ++bt)
                ldx4(bf[bt], Bb + brow[bt] + ((c8 ^ bbit[bt]) << 4));
#pragma unroll
            for (int mt = 0; mt < 4; ++mt)
#pragma unroll
                for (int nt = 0; nt < 4; ++nt)
                    mma16816(acc[mt][nt], af[mt],
                             bf[nt >> 1][nt & 1], bf[nt >> 1][(nt & 1) + 2]);
        }
        __syncthreads();
    }

    // ---- epilogue: bias add + store (f32) ----
    int r0base = m_base + wm * 64 + (lane >> 2);
    int colb   = n_base + wn * 32 + ((lane & 3) << 1);
    float2 bs[4];
#pragma unroll
    for (int nt = 0; nt < 4; ++nt)
        bs[nt] = *(const float2*)(bias + colb + nt * 8);
#pragma unroll
    for (int mt = 0; mt < 4; ++mt) {
        int r0 = r0base + mt * 16;
        int r1 = r0 + 8;
#pragma unroll
        for (int nt = 0; nt < 4; ++nt) {
            int col = colb + nt * 8;
            float2 v0 = { acc[mt][nt][0] + bs[nt].x, acc[mt][nt][1] + bs[nt].y };
            float2 v1 = { acc[mt][nt][2] + bs[nt].x, acc[mt][nt][3] + bs[nt].y };
            *(float2*)(out + (size_t)r0 * OUT_FEAT + col) = v0;
            *(float2*)(out + (size_t)r1 * OUT_FEAT + col) = v1;
        }
    }
}

// ================= launcher =================
extern "C" void kernel_launch(void* const* d_in, const int* in_sizes, int n_in,
                              void* d_out, int out_size) {
    const float* x        = (const float*)d_in[0];
    const float* base_w   = (const float*)d_in[1];
    const float* base_b   = (const float*)d_in[2];
    const float* spline_w = (const float*)d_in[3];
    float* out = (float*)d_out;

    (void)in_sizes; (void)n_in; (void)out_size;

    kan_wprep<<<(OUT_FEAT * KTOT) / 256, 256>>>(base_w, spline_w);
    kan_act  <<<(BATCH * IN_FEAT) / 256, 256>>>(x);

    cudaFuncSetAttribute(kan_gemm, cudaFuncAttributeMaxDynamicSharedMemorySize,
                         SMEM_TOTAL);
    kan_gemm<<<(BATCH / TILE_M) * (OUT_FEAT / TILE_N), 256, SMEM_TOTAL>>>(base_b, out);
}

// round 8
// speedup vs baseline: 1.0310x; 1.0310x over previous
#include <cuda_runtime.h>
#include <cuda_fp16.h>

// ---------------- problem constants ----------------
#define BATCH    8192
#define IN_FEAT  512
#define OUT_FEAT 512
#define GK       13                       // GRID_SIZE + K
#define KTOT     (IN_FEAT + IN_FEAT*GK)   // 7168
#define ROWBYTES (KTOT * 2)               // 14336 bytes per fp16 row
#define KCHUNK   64                       // fp16 elems per stage chunk = 128B
#define NCHUNKS  (KTOT / KCHUNK)          // 112
#define TILE_M   128
#define TILE_N   128
#define STAGES   3

// ---------------- scratch (device globals; no allocation allowed) ------
__device__ __half g_act[(size_t)BATCH * KTOT];     // 117 MB activation matrix
__device__ __half g_wk [(size_t)OUT_FEAT * KTOT];  // 7.3 MB packed weights

// ---------------- helpers ----------------
__device__ __forceinline__ unsigned smem_u32(const void* p) {
    unsigned a;
    asm("{ .reg .u64 t; cvta.to.shared.u64 t, %1; cvt.u32.u64 %0, t; }"
        : "=r"(a) : "l"(p));
    return a;
}
__device__ __forceinline__ void cp16(unsigned saddr, const void* gaddr) {
    asm volatile("cp.async.cg.shared.global [%0], [%1], 16;"
                 :: "r"(saddr), "l"(gaddr));
}
__device__ __forceinline__ void cp_commit() {
    asm volatile("cp.async.commit_group;");
}
template <int N>
__device__ __forceinline__ void cp_wait() {
    asm volatile("cp.async.wait_group %0;" :: "n"(N));
}
__device__ __forceinline__ void ldx4(unsigned* r, unsigned addr) {
    asm volatile("ldmatrix.sync.aligned.m8n8.x4.shared.b16 {%0,%1,%2,%3}, [%4];"
                 : "=r"(r[0]), "=r"(r[1]), "=r"(r[2]), "=r"(r[3]) : "r"(addr));
}
__device__ __forceinline__ void mma16816(float* d, const unsigned* a,
                                         unsigned b0, unsigned b1) {
    asm volatile(
        "mma.sync.aligned.m16n8k16.row.col.f32.f16.f16.f32 "
        "{%0,%1,%2,%3}, {%4,%5,%6,%7}, {%8,%9}, {%0,%1,%2,%3};"
        : "+f"(d[0]), "+f"(d[1]), "+f"(d[2]), "+f"(d[3])
        : "r"(a[0]), "r"(a[1]), "r"(a[2]), "r"(a[3]), "r"(b0), "r"(b1));
}

// ========= kernel 0: pack weights + build activation matrix (merged) =========
// blocks [0, WBLK): pack [base_w | spline_w] -> g_wk (fp16)
// blocks [WBLK, WBLK+ABLK): g_act = [silu(x) | uniform cubic B-spline bases]
#define WBLK ((OUT_FEAT * KTOT) / 256)    // 14336
#define ABLK ((BATCH * IN_FEAT) / 256)    // 16384

__global__ void kan_prep(const float* __restrict__ x,
                         const float* __restrict__ base_w,
                         const float* __restrict__ spline_w) {
    if (blockIdx.x < WBLK) {
        size_t idx = (size_t)blockIdx.x * 256 + threadIdx.x;
        int o = (int)(idx / KTOT);
        int k = (int)(idx % KTOT);
        float v = (k < IN_FEAT)
            ? base_w[(size_t)o * IN_FEAT + k]
            : spline_w[(size_t)o * (IN_FEAT * GK) + (k - IN_FEAT)];
        g_wk[idx] = __float2half_rn(v);
        return;
    }
    size_t idx = (size_t)(blockIdx.x - WBLK) * 256 + threadIdx.x;
    int b = (int)(idx / IN_FEAT);
    int i = (int)(idx % IN_FEAT);
    float xv = x[idx];

    __half* row = g_act + (size_t)b * KTOT;
    row[i] = __float2half_rn(xv / (1.0f + __expf(-xv)));   // silu branch

    // knots t_j = -3.2 + 0.4 j (j = 0..16); closed-form cubic B-spline weights
    float t = (xv + 3.2f) * 2.5f;
    float w0 = 0.f, w1 = 0.f, w2 = 0.f, w3 = 0.f;
    int g0 = -100;                                         // out of range -> zeros
    if (t >= 0.0f && t < 16.0f) {
        int j = (int)t;
        float u  = t - (float)j;
        float um = 1.0f - u;
        float u2 = u * u, u3 = u2 * u;
        float um3 = um * um * um;
        const float c6 = 1.0f / 6.0f;
        w0 = um3 * c6;                                        // basis j-3
        w1 = (3.0f * u3 - 6.0f * u2 + 4.0f) * c6;             // basis j-2
        w2 = (-3.0f * u3 + 3.0f * u2 + 3.0f * u + 1.0f) * c6; // basis j-1
        w3 = u3 * c6;                                         // basis j
        g0 = j - 3;
    }
    __half* sp = row + IN_FEAT + (size_t)i * GK;
#pragma unroll
    for (int g = 0; g < GK; ++g) {
        int m = g - g0;
        float v = (m == 0) ? w0 : (m == 1) ? w1 : (m == 2) ? w2 : (m == 3) ? w3 : 0.0f;
        sp[g] = __float2half_rn(v);
    }
}

// ================= kernel 1: fp16 mma.sync GEMM + bias =================
// C[8192,512] = Act[8192,7168] * Wk[512,7168]^T + bias
#define A_BYTES     (TILE_M * KCHUNK * 2)        // 16384
#define B_BYTES     (TILE_N * KCHUNK * 2)        // 16384
#define STAGE_BYTES (A_BYTES + B_BYTES)          // 32768
#define SMEM_TOTAL  (STAGES * STAGE_BYTES)       // 98304

__global__ void __launch_bounds__(256, 2)
kan_gemm(const float* __restrict__ bias, float* __restrict__ out) {
    extern __shared__ char smem[];
    unsigned sb = smem_u32(smem);
    int tid  = threadIdx.x;
    int w    = tid >> 5;
    int lane = tid & 31;
    int wm   = w >> 2;          // 0..1  (M direction, 64 rows each)
    int wn   = w & 3;           // 0..3  (N direction, 32 cols each)

    int m_base = (blockIdx.x >> 2) * TILE_M;
    int n_base = (blockIdx.x & 3) * TILE_N;

    // ---- cp.async loader precompute: 4 groups of 16B per thread per tile ----
    unsigned so[4];
    const char* ga[4];
    const char* gb[4];
#pragma unroll
    for (int q = 0; q < 4; ++q) {
        int g   = tid + q * 256;          // 0..1023
        int row = g >> 3;                 // 0..127
        int c8  = g & 7;                  // 16B column
        so[q] = (unsigned)((row << 7) + (((unsigned)c8 ^ (row & 7)) << 4));
        ga[q] = (const char*)g_act + (size_t)(m_base + row) * ROWBYTES + c8 * 16;
        gb[q] = (const char*)g_wk  + (size_t)(n_base + row) * ROWBYTES + c8 * 16;
    }

    // ---- ldmatrix per-lane precompute ----
    int lrow = lane & 15;
    unsigned lh = (unsigned)(lane >> 4);
    unsigned arow[4], abit[4];
#pragma unroll
    for (int mt = 0; mt < 4; ++mt) {
        int r = wm * 64 + mt * 16 + lrow;
        arow[mt] = (unsigned)(r << 7);
        abit[mt] = (unsigned)(r & 7);
    }
    unsigned brow[2], bbit[2];
#pragma unroll
    for (int bt = 0; bt < 2; ++bt) {
        int r = wn * 32 + bt * 16 + lrow;
        brow[bt] = (unsigned)(r << 7);
        bbit[bt] = (unsigned)(r & 7);
    }

    float acc[4][4][4];
#pragma unroll
    for (int mt = 0; mt < 4; ++mt)
#pragma unroll
        for (int nt = 0; nt < 4; ++nt)
#pragma unroll
            for (int e = 0; e < 4; ++e) acc[mt][nt][e] = 0.0f;

    // ---- prologue: issue chunks 0 and 1 into stages 0 and 1 ----
#pragma unroll
    for (int p = 0; p < 2; ++p) {
        unsigned base = sb + p * STAGE_BYTES;
        size_t koff = (size_t)p * 128;
#pragma unroll
        for (int q = 0; q < 4; ++q) cp16(base + so[q], ga[q] + koff);
#pragma unroll
        for (int q = 0; q < 4; ++q) cp16(base + A_BYTES + so[q], gb[q] + koff);
        cp_commit();
    }

    int s_cur = 0;   // stage of chunk c
    int s_nxt = 2;   // stage of chunk c+2 (write target)
    for (int c = 0; c < NCHUNKS; ++c) {
        if (c < NCHUNKS - 1) cp_wait<1>(); else cp_wait<0>();
        __syncthreads();   // all warps done with the stage we are about to refill

        if (c + 2 < NCHUNKS) {
            unsigned base = sb + s_nxt * STAGE_BYTES;
            size_t koff = (size_t)(c + 2) * 128;
#pragma unroll
            for (int q = 0; q < 4; ++q) cp16(base + so[q], ga[q] + koff);
#pragma unroll
            for (int q = 0; q < 4; ++q) cp16(base + A_BYTES + so[q], gb[q] + koff);
            cp_commit();
        }

        unsigned Ab = sb + s_cur * STAGE_BYTES;
        unsigned Bb = Ab + A_BYTES;
#pragma unroll
        for (int kt = 0; kt < 4; ++kt) {
            unsigned c8 = (unsigned)(kt * 2) + lh;
            unsigned af[4][4];
#pragma unroll
            for (int mt = 0; mt < 4; ++mt)
                ldx4(af[mt], Ab + arow[mt] + ((c8 ^ abit[mt]) << 4));
            unsigned bf[2][4];
#pragma unroll
            for (int bt = 0; bt < 2; ++bt)
                ldx4(bf[bt], Bb + brow[bt] + ((c8 ^ bbit[bt]) << 4));
#pragma unroll
            for (int mt = 0; mt < 4; ++mt)
#pragma unroll
                for (int nt = 0; nt < 4; ++nt)
                    mma16816(acc[mt][nt], af[mt],
                             bf[nt >> 1][nt & 1], bf[nt >> 1][(nt & 1) + 2]);
        }

        s_cur = (s_cur == STAGES - 1) ? 0 : s_cur + 1;
        s_nxt = (s_nxt == STAGES - 1) ? 0 : s_nxt + 1;
    }

    // ---- epilogue: bias add + store (f32) ----
    int r0base = m_base + wm * 64 + (lane >> 2);
    int colb   = n_base + wn * 32 + ((lane & 3) << 1);
    float2 bs[4];
#pragma unroll
    for (int nt = 0; nt < 4; ++nt)
        bs[nt] = *(const float2*)(bias + colb + nt * 8);
#pragma unroll
    for (int mt = 0; mt < 4; ++mt) {
        int r0 = r0base + mt * 16;
        int r1 = r0 + 8;
#pragma unroll
        for (int nt = 0; nt < 4; ++nt) {
            int col = colb + nt * 8;
            float2 v0 = { acc[mt][nt][0] + bs[nt].x, acc[mt][nt][1] + bs[nt].y };
            float2 v1 = { acc[mt][nt][2] + bs[nt].x, acc[mt][nt][3] + bs[nt].y };
            *(float2*)(out + (size_t)r0 * OUT_FEAT + col) = v0;
            *(float2*)(out + (size_t)r1 * OUT_FEAT + col) = v1;
        }
    }
}

// ================= launcher =================
extern "C" void kernel_launch(void* const* d_in, const int* in_sizes, int n_in,
                              void* d_out, int out_size) {
    const float* x        = (const float*)d_in[0];
    const float* base_w   = (const float*)d_in[1];
    const float* base_b   = (const float*)d_in[2];
    const float* spline_w = (const float*)d_in[3];
    float* out = (float*)d_out;

    (void)in_sizes; (void)n_in; (void)out_size;

    kan_prep<<<WBLK + ABLK, 256>>>(x, base_w, spline_w);

    cudaFuncSetAttribute(kan_gemm, cudaFuncAttributeMaxDynamicSharedMemorySize,
                         SMEM_TOTAL);
    kan_gemm<<<(BATCH / TILE_M) * (OUT_FEAT / TILE_N), 256, SMEM_TOTAL>>>(base_b, out);
}

// round 9
// speedup vs baseline: 1.6218x; 1.5731x over previous
#include <cuda_runtime.h>
#include <cuda_fp16.h>

// ---------------- problem constants ----------------
#define BATCH    8192
#define IN_FEAT  512
#define OUT_FEAT 512
#define GK       13                       // GRID_SIZE + K
#define KTOT     (IN_FEAT + IN_FEAT*GK)   // 7168
#define ROWBYTES (KTOT * 2)               // 14336 bytes per fp16 row
#define KCHUNK   64                       // fp16 elems per stage chunk = 128B
#define NCHUNKS  (KTOT / KCHUNK)          // 112
#define TILE_M   128
#define TILE_N   128
#define STAGES   3

// ---------------- scratch (device globals; no allocation allowed) ------
__device__ __half g_act[(size_t)BATCH * KTOT];     // 117 MB activation matrix
__device__ __half g_wk [(size_t)OUT_FEAT * KTOT];  // 7.3 MB packed weights

// ---------------- helpers ----------------
__device__ __forceinline__ unsigned smem_u32(const void* p) {
    unsigned a;
    asm("{ .reg .u64 t; cvta.to.shared.u64 t, %1; cvt.u32.u64 %0, t; }"
        : "=r"(a) : "l"(p));
    return a;
}
__device__ __forceinline__ void cp16(unsigned saddr, const void* gaddr) {
    asm volatile("cp.async.cg.shared.global [%0], [%1], 16;"
                 :: "r"(saddr), "l"(gaddr));
}
__device__ __forceinline__ void cp_commit() {
    asm volatile("cp.async.commit_group;");
}
template <int N>
__device__ __forceinline__ void cp_wait() {
    asm volatile("cp.async.wait_group %0;" :: "n"(N));
}
__device__ __forceinline__ void ldx4(unsigned* r, unsigned addr) {
    asm volatile("ldmatrix.sync.aligned.m8n8.x4.shared.b16 {%0,%1,%2,%3}, [%4];"
                 : "=r"(r[0]), "=r"(r[1]), "=r"(r[2]), "=r"(r[3]) : "r"(addr));
}
__device__ __forceinline__ void mma16816(float* d, const unsigned* a,
                                         unsigned b0, unsigned b1) {
    asm volatile(
        "mma.sync.aligned.m16n8k16.row.col.f32.f16.f16.f32 "
        "{%0,%1,%2,%3}, {%4,%5,%6,%7}, {%8,%9}, {%0,%1,%2,%3};"
        : "+f"(d[0]), "+f"(d[1]), "+f"(d[2]), "+f"(d[3])
        : "r"(a[0]), "r"(a[1]), "r"(a[2]), "r"(a[3]), "r"(b0), "r"(b1));
}

// ============ kernel 0: pack weights -> fp16 (8-wide vectorized) ============
// Each thread handles 8 consecutive k of one output row o. Since 8 | IN_FEAT,
// a group never straddles the base/spline boundary.
#define WELEMS  ((OUT_FEAT * KTOT) / 8)   // 458752 groups
__global__ void kan_wprep(const float* __restrict__ base_w,
                          const float* __restrict__ spline_w) {
    size_t gidx = (size_t)blockIdx.x * blockDim.x + threadIdx.x;
    if (gidx >= WELEMS) return;
    size_t e = gidx * 8;
    int o  = (int)(e / KTOT);
    int k0 = (int)(e % KTOT);
    const float* src = (k0 < IN_FEAT)
        ? base_w + (size_t)o * IN_FEAT + k0
        : spline_w + (size_t)o * (IN_FEAT * GK) + (k0 - IN_FEAT);
    float4 a = *(const float4*)(src);
    float4 b = *(const float4*)(src + 4);
    __half h[8];
    h[0] = __float2half_rn(a.x); h[1] = __float2half_rn(a.y);
    h[2] = __float2half_rn(a.z); h[3] = __float2half_rn(a.w);
    h[4] = __float2half_rn(b.x); h[5] = __float2half_rn(b.y);
    h[6] = __float2half_rn(b.z); h[7] = __float2half_rn(b.w);
    *(int4*)(g_wk + e) = *(int4*)h;
}

// ===== kernel 1: activations = [silu(x) | uniform cubic B-spline bases] =====
// One block per batch row. Build the full fp16 row in smem (2B smem writes),
// then stream it out with coalesced 16B stores.
__global__ void __launch_bounds__(256)
kan_act(const float* __restrict__ x) {
    __shared__ __half s[KTOT];             // 14336 B row image
    int b = blockIdx.x;
    const float* xr = x + (size_t)b * IN_FEAT;

#pragma unroll 2
    for (int i = threadIdx.x; i < IN_FEAT; i += 256) {
        float xv = xr[i];
        s[i] = __float2half_rn(xv / (1.0f + __expf(-xv)));   // silu branch

        // knots t_j = -3.2 + 0.4 j (j = 0..16); closed-form cubic B-spline
        float t = (xv + 3.2f) * 2.5f;
        float w0 = 0.f, w1 = 0.f, w2 = 0.f, w3 = 0.f;
        int g0 = -100;                                       // out of range
        if (t >= 0.0f && t < 16.0f) {
            int j = (int)t;
            float u  = t - (float)j;
            float um = 1.0f - u;
            float u2 = u * u, u3 = u2 * u;
            float um3 = um * um * um;
            const float c6 = 1.0f / 6.0f;
            w0 = um3 * c6;                                        // basis j-3
            w1 = (3.0f * u3 - 6.0f * u2 + 4.0f) * c6;             // basis j-2
            w2 = (-3.0f * u3 + 3.0f * u2 + 3.0f * u + 1.0f) * c6; // basis j-1
            w3 = u3 * c6;                                         // basis j
            g0 = j - 3;
        }
        __half* sp = s + IN_FEAT + i * GK;
#pragma unroll
        for (int g = 0; g < GK; ++g) {
            int m = g - g0;
            float v = (m == 0) ? w0 : (m == 1) ? w1 : (m == 2) ? w2
                    : (m == 3) ? w3 : 0.0f;
            sp[g] = __float2half_rn(v);
        }
    }
    __syncthreads();

    const int4* src = (const int4*)s;
    int4* dst = (int4*)(g_act + (size_t)b * KTOT);
#pragma unroll 4
    for (int q = threadIdx.x; q < ROWBYTES / 16; q += 256)   // 896 int4
        dst[q] = src[q];
}

// ================= kernel 2: fp16 mma.sync GEMM + bias =================
// C[8192,512] = Act[8192,7168] * Wk[512,7168]^T + bias
#define A_BYTES     (TILE_M * KCHUNK * 2)        // 16384
#define B_BYTES     (TILE_N * KCHUNK * 2)        // 16384
#define STAGE_BYTES (A_BYTES + B_BYTES)          // 32768
#define SMEM_TOTAL  (STAGES * STAGE_BYTES)       // 98304

__global__ void __launch_bounds__(256, 2)
kan_gemm(const float* __restrict__ bias, float* __restrict__ out) {
    extern __shared__ char smem[];
    unsigned sb = smem_u32(smem);
    int tid  = threadIdx.x;
    int w    = tid >> 5;
    int lane = tid & 31;
    int wm   = w >> 2;          // 0..1  (M direction, 64 rows each)
    int wn   = w & 3;           // 0..3  (N direction, 32 cols each)

    int m_base = (blockIdx.x >> 2) * TILE_M;
    int n_base = (blockIdx.x & 3) * TILE_N;

    // ---- cp.async loader precompute: 4 groups of 16B per thread per tile ----
    unsigned so[4];
    const char* ga[4];
    const char* gb[4];
#pragma unroll
    for (int q = 0; q < 4; ++q) {
        int g   = tid + q * 256;          // 0..1023
        int row = g >> 3;                 // 0..127
        int c8  = g & 7;                  // 16B column
        so[q] = (unsigned)((row << 7) + (((unsigned)c8 ^ (row & 7)) << 4));
        ga[q] = (const char*)g_act + (size_t)(m_base + row) * ROWBYTES + c8 * 16;
        gb[q] = (const char*)g_wk  + (size_t)(n_base + row) * ROWBYTES + c8 * 16;
    }

    // ---- ldmatrix per-lane precompute ----
    int lrow = lane & 15;
    unsigned lh = (unsigned)(lane >> 4);
    unsigned arow[4], abit[4];
#pragma unroll
    for (int mt = 0; mt < 4; ++mt) {
        int r = wm * 64 + mt * 16 + lrow;
        arow[mt] = (unsigned)(r << 7);
        abit[mt] = (unsigned)(r & 7);
    }
    unsigned brow[2], bbit[2];
#pragma unroll
    for (int bt = 0; bt < 2; ++bt) {
        int r = wn * 32 + bt * 16 + lrow;
        brow[bt] = (unsigned)(r << 7);
        bbit[bt] = (unsigned)(r & 7);
    }

    float acc[4][4][4];
#pragma unroll
    for (int mt = 0; mt < 4; ++mt)
#pragma unroll
        for (int nt = 0; nt < 4; ++nt)
#pragma unroll
            for (int e = 0; e < 4; ++e) acc[mt][nt][e] = 0.0f;

    // ---- prologue: issue chunks 0 and 1 into stages 0 and 1 ----
#pragma unroll
    for (int p = 0; p < 2; ++p) {
        unsigned base = sb + p * STAGE_BYTES;
        size_t koff = (size_t)p * 128;
#pragma unroll
        for (int q = 0; q < 4; ++q) cp16(base + so[q], ga[q] + koff);
#pragma unroll
        for (int q = 0; q < 4; ++q) cp16(base + A_BYTES + so[q], gb[q] + koff);
        cp_commit();
    }

    int s_cur = 0;   // stage of chunk c
    int s_nxt = 2;   // stage of chunk c+2 (write target)
    for (int c = 0; c < NCHUNKS; ++c) {
        if (c < NCHUNKS - 1) cp_wait<1>(); else cp_wait<0>();
        __syncthreads();   // all warps done with the stage we are about to refill

        if (c + 2 < NCHUNKS) {
            unsigned base = sb + s_nxt * STAGE_BYTES;
            size_t koff = (size_t)(c + 2) * 128;
#pragma unroll
            for (int q = 0; q < 4; ++q) cp16(base + so[q], ga[q] + koff);
#pragma unroll
            for (int q = 0; q < 4; ++q) cp16(base + A_BYTES + so[q], gb[q] + koff);
            cp_commit();
        }

        unsigned Ab = sb + s_cur * STAGE_BYTES;
        unsigned Bb = Ab + A_BYTES;
#pragma unroll
        for (int kt = 0; kt < 4; ++kt) {
            unsigned c8 = (unsigned)(kt * 2) + lh;
            unsigned af[4][4];
#pragma unroll
            for (int mt = 0; mt < 4; ++mt)
                ldx4(af[mt], Ab + arow[mt] + ((c8 ^ abit[mt]) << 4));
            unsigned bf[2][4];
#pragma unroll
            for (int bt = 0; bt < 2; ++bt)
                ldx4(bf[bt], Bb + brow[bt] + ((c8 ^ bbit[bt]) << 4));
#pragma unroll
            for (int mt = 0; mt < 4; ++mt)
#pragma unroll
                for (int nt = 0; nt < 4; ++nt)
                    mma16816(acc[mt][nt], af[mt],
                             bf[nt >> 1][nt & 1], bf[nt >> 1][(nt & 1) + 2]);
        }

        s_cur = (s_cur == STAGES - 1) ? 0 : s_cur + 1;
        s_nxt = (s_nxt == STAGES - 1) ? 0 : s_nxt + 1;
    }

    // ---- epilogue: bias add + store (f32) ----
    int r0base = m_base + wm * 64 + (lane >> 2);
    int colb   = n_base + wn * 32 + ((lane & 3) << 1);
    float2 bs[4];
#pragma unroll
    for (int nt = 0; nt < 4; ++nt)
        bs[nt] = *(const float2*)(bias + colb + nt * 8);
#pragma unroll
    for (int mt = 0; mt < 4; ++mt) {
        int r0 = r0base + mt * 16;
        int r1 = r0 + 8;
#pragma unroll
        for (int nt = 0; nt < 4; ++nt) {
            int col = colb + nt * 8;
            float2 v0 = { acc[mt][nt][0] + bs[nt].x, acc[mt][nt][1] + bs[nt].y };
            float2 v1 = { acc[mt][nt][2] + bs[nt].x, acc[mt][nt][3] + bs[nt].y };
            *(float2*)(out + (size_t)r0 * OUT_FEAT + col) = v0;
            *(float2*)(out + (size_t)r1 * OUT_FEAT + col) = v1;
        }
    }
}

// ================= launcher =================
extern "C" void kernel_launch(void* const* d_in, const int* in_sizes, int n_in,
                              void* d_out, int out_size) {
    const float* x        = (const float*)d_in[0];
    const float* base_w   = (const float*)d_in[1];
    const float* base_b   = (const float*)d_in[2];
    const float* spline_w = (const float*)d_in[3];
    float* out = (float*)d_out;

    (void)in_sizes; (void)n_in; (void)out_size;

    kan_wprep<<<(WELEMS + 255) / 256, 256>>>(base_w, spline_w);
    kan_act<<<BATCH, 256>>>(x);

    cudaFuncSetAttribute(kan_gemm, cudaFuncAttributeMaxDynamicSharedMemorySize,
                         SMEM_TOTAL);
    kan_gemm<<<(BATCH / TILE_M) * (OUT_FEAT / TILE_N), 256, SMEM_TOTAL>>>(base_b, out);
}

// round 10
// speedup vs baseline: 1.6718x; 1.0308x over previous
#include <cuda_runtime.h>
#include <cuda_fp16.h>

// ---------------- problem constants ----------------
#define BATCH    8192
#define IN_FEAT  512
#define OUT_FEAT 512
#define GK       13                       // GRID_SIZE + K
#define KTOT     (IN_FEAT + IN_FEAT*GK)   // 7168
#define ROWBYTES (KTOT * 2)               // 14336 bytes per fp16 row
#define KCHUNK   64                       // fp16 elems per stage chunk = 128B
#define NCHUNKS  (KTOT / KCHUNK)          // 112
#define TILE_M   256
#define TILE_N   128
#define STAGES   4

// NOTE: k-index layout is permuted (transparently to the GEMM):
//   k' in [0,512)            -> silu(x_i),             i = k'
//   k' in [512, 7168)        -> basis_g(x_i),  g = (k'-512)/512, i = (k'-512)%512
// g_wk uses the identical permutation, so the dot product is unchanged.

// ---------------- scratch (device globals; no allocation allowed) ------
__device__ __half g_act[(size_t)BATCH * KTOT];     // 117 MB activation matrix
__device__ __half g_wk [(size_t)OUT_FEAT * KTOT];  // 7.3 MB packed weights

// ---------------- helpers ----------------
__device__ __forceinline__ unsigned smem_u32(const void* p) {
    unsigned a;
    asm("{ .reg .u64 t; cvta.to.shared.u64 t, %1; cvt.u32.u64 %0, t; }"
        : "=r"(a) : "l"(p));
    return a;
}
__device__ __forceinline__ void cp16(unsigned saddr, const void* gaddr) {
    asm volatile("cp.async.cg.shared.global [%0], [%1], 16;"
                 :: "r"(saddr), "l"(gaddr));
}
__device__ __forceinline__ void cp_commit() {
    asm volatile("cp.async.commit_group;");
}
template <int N>
__device__ __forceinline__ void cp_wait() {
    asm volatile("cp.async.wait_group %0;" :: "n"(N));
}
__device__ __forceinline__ void ldx4(unsigned* r, unsigned addr) {
    asm volatile("ldmatrix.sync.aligned.m8n8.x4.shared.b16 {%0,%1,%2,%3}, [%4];"
                 : "=r"(r[0]), "=r"(r[1]), "=r"(r[2]), "=r"(r[3]) : "r"(addr));
}
__device__ __forceinline__ void mma16816(float* d, const unsigned* a,
                                         unsigned b0, unsigned b1) {
    asm volatile(
        "mma.sync.aligned.m16n8k16.row.col.f32.f16.f16.f32 "
        "{%0,%1,%2,%3}, {%4,%5,%6,%7}, {%8,%9}, {%0,%1,%2,%3};"
        : "+f"(d[0]), "+f"(d[1]), "+f"(d[2]), "+f"(d[3])
        : "r"(a[0]), "r"(a[1]), "r"(a[2]), "r"(a[3]), "r"(b0), "r"(b1));
}

// ======== kernel 0: pack weights -> fp16, permuted (g-major spline) ========
// One block per output row o. Spline block needs the (i,g)->(g,i) transpose:
// stage in smem padded to stride 14 (conflict-free halves).
__global__ void __launch_bounds__(256)
kan_wprep(const float* __restrict__ base_w, const float* __restrict__ spline_w) {
    __shared__ __half s[IN_FEAT * 14];     // 14336 B
    int o = blockIdx.x;
    int tid = threadIdx.x;

    const float* bw = base_w + (size_t)o * IN_FEAT;
    __half* dstb = g_wk + (size_t)o * KTOT;
#pragma unroll
    for (int i = tid; i < IN_FEAT; i += 256)
        dstb[i] = __float2half_rn(bw[i]);

    const float* sw = spline_w + (size_t)o * (IN_FEAT * GK);
    for (int idx = tid; idx < IN_FEAT * GK; idx += 256) {
        int i = idx / GK, g = idx % GK;    // coalesced read
        s[i * 14 + g] = __float2half_rn(sw[idx]);
    }
    __syncthreads();

    __half* dsts = dstb + IN_FEAT;
    for (int idx = tid; idx < IN_FEAT * GK; idx += 256) {
        int g = idx >> 9, i = idx & 511;   // k' = g*512 + i  (coalesced write)
        dsts[idx] = s[i * 14 + g];
    }
}

// ===== kernel 1: activations, permuted layout, fully coalesced stores =====
// Each thread handles one pair (i, i+1) of one batch row: 14 half2 stores,
// all warp-contiguous.
__global__ void __launch_bounds__(256)
kan_act(const float* __restrict__ x) {
    int p   = blockIdx.x * 256 + threadIdx.x;     // pair index
    int b   = p >> 8;                             // 256 pairs per row
    int ip2 = p & 255;                            // half2 slot within 512 feats
    float2 xv = *(const float2*)(x + (size_t)b * IN_FEAT + ip2 * 2);

    __half2* row2 = (__half2*)(g_act + (size_t)b * KTOT);
    float s0 = xv.x / (1.0f + __expf(-xv.x));
    float s1 = xv.y / (1.0f + __expf(-xv.y));
    row2[ip2] = __floats2half2_rn(s0, s1);

    // closed-form uniform cubic B-spline weights for both elements
    float w[2][4];
    int   g0[2];
    float xs[2] = { xv.x, xv.y };
#pragma unroll
    for (int e = 0; e < 2; ++e) {
        float t = (xs[e] + 3.2f) * 2.5f;
        w[e][0] = w[e][1] = w[e][2] = w[e][3] = 0.0f;
        g0[e] = -100;
        if (t >= 0.0f && t < 16.0f) {
            int j = (int)t;
            float u  = t - (float)j;
            float um = 1.0f - u;
            float u2 = u * u, u3 = u2 * u;
            float um3 = um * um * um;
            const float c6 = 1.0f / 6.0f;
            w[e][0] = um3 * c6;
            w[e][1] = (3.0f * u3 - 6.0f * u2 + 4.0f) * c6;
            w[e][2] = (-3.0f * u3 + 3.0f * u2 + 3.0f * u + 1.0f) * c6;
            w[e][3] = u3 * c6;
            g0[e] = j - 3;
        }
    }
#pragma unroll
    for (int g = 0; g < GK; ++g) {
        int m0 = g - g0[0], m1 = g - g0[1];
        float v0 = (m0 == 0) ? w[0][0] : (m0 == 1) ? w[0][1]
                 : (m0 == 2) ? w[0][2] : (m0 == 3) ? w[0][3] : 0.0f;
        float v1 = (m1 == 0) ? w[1][0] : (m1 == 1) ? w[1][1]
                 : (m1 == 2) ? w[1][2] : (m1 == 3) ? w[1][3] : 0.0f;
        row2[256 + g * 256 + ip2] = __floats2half2_rn(v0, v1);
    }
}

// ================= kernel 2: fp16 mma.sync GEMM + bias =================
// C[8192,512] = Act[8192,7168] * Wk[512,7168]^T + bias
// CTA tile 256x128, 8 warps of 64x64, 4-stage cp.async ring, 1 CTA/SM.
#define A_BYTES     (TILE_M * KCHUNK * 2)        // 32768
#define B_BYTES     (TILE_N * KCHUNK * 2)        // 16384
#define STAGE_BYTES (A_BYTES + B_BYTES)          // 49152
#define SMEM_TOTAL  (STAGES * STAGE_BYTES)       // 196608

__global__ void __launch_bounds__(256, 1)
kan_gemm(const float* __restrict__ bias, float* __restrict__ out) {
    extern __shared__ char smem[];
    unsigned sb = smem_u32(smem);
    int tid  = threadIdx.x;
    int w    = tid >> 5;
    int lane = tid & 31;
    int wm   = w >> 1;          // 0..3  (M direction, 64 rows each)
    int wn   = w & 1;           // 0..1  (N direction, 64 cols each)

    int m_base = (blockIdx.x >> 2) * TILE_M;
    int n_base = (blockIdx.x & 3) * TILE_N;

    // ---- cp.async loader precompute ----
    // flat group g = tid + q*256; q 0..7 -> A (rows 0..255), q 8..11 -> B.
    // row(q) = tid>>3 + (q%8)*32, c8 = tid&7; swizzle invariant in q (row&7).
    int  row0 = tid >> 3;
    int  c8   = tid & 7;
    unsigned so = (unsigned)((row0 << 7) + (((unsigned)c8 ^ (row0 & 7)) << 4));
    const char* gA = (const char*)g_act + (size_t)(m_base + row0) * ROWBYTES + c8 * 16;
    const char* gB = (const char*)g_wk  + (size_t)(n_base + row0) * ROWBYTES + c8 * 16;

    // ---- ldmatrix per-lane precompute ----
    int lrow = lane & 15;
    unsigned lh = (unsigned)(lane >> 4);
    unsigned arow[4], abit[4], brow[4], bbit[4];
#pragma unroll
    for (int mt = 0; mt < 4; ++mt) {
        int r = wm * 64 + mt * 16 + lrow;
        arow[mt] = (unsigned)(r << 7);
        abit[mt] = (unsigned)(r & 7);
    }
#pragma unroll
    for (int bt = 0; bt < 4; ++bt) {
        int r = wn * 64 + bt * 16 + lrow;
        brow[bt] = (unsigned)(r << 7);
        bbit[bt] = (unsigned)(r & 7);
    }

    float acc[4][8][4];
#pragma unroll
    for (int mt = 0; mt < 4; ++mt)
#pragma unroll
        for (int nt = 0; nt < 8; ++nt)
#pragma unroll
            for (int e = 0; e < 4; ++e) acc[mt][nt][e] = 0.0f;

    // ---- prologue: issue chunks 0..2 into stages 0..2 ----
#pragma unroll
    for (int p = 0; p < STAGES - 1; ++p) {
        unsigned base = sb + p * STAGE_BYTES;
        size_t koff = (size_t)p * 128;
#pragma unroll
        for (int q = 0; q < 8; ++q)
            cp16(base + so + q * 4096, gA + (size_t)q * 32 * ROWBYTES + koff);
#pragma unroll
        for (int q = 0; q < 4; ++q)
            cp16(base + A_BYTES + so + q * 4096, gB + (size_t)q * 32 * ROWBYTES + koff);
        cp_commit();
    }

    for (int c = 0; c < NCHUNKS; ++c) {
        if (c < NCHUNKS - 2)      cp_wait<2>();
        else if (c == NCHUNKS - 2) cp_wait<1>();
        else                       cp_wait<0>();
        __syncthreads();

        if (c + STAGES - 1 < NCHUNKS) {
            unsigned base = sb + ((c + STAGES - 1) & (STAGES - 1)) * STAGE_BYTES;
            size_t koff = (size_t)(c + STAGES - 1) * 128;
#pragma unroll
            for (int q = 0; q < 8; ++q)
                cp16(base + so + q * 4096, gA + (size_t)q * 32 * ROWBYTES + koff);
#pragma unroll
            for (int q = 0; q < 4; ++q)
                cp16(base + A_BYTES + so + q * 4096, gB + (size_t)q * 32 * ROWBYTES + koff);
            cp_commit();
        }

        unsigned Ab = sb + (c & (STAGES - 1)) * STAGE_BYTES;
        unsigned Bb = Ab + A_BYTES;
#pragma unroll
        for (int kt = 0; kt < 4; ++kt) {
            unsigned kc8 = (unsigned)(kt * 2) + lh;
            unsigned af[4][4];
#pragma unroll
            for (int mt = 0; mt < 4; ++mt)
                ldx4(af[mt], Ab + arow[mt] + ((kc8 ^ abit[mt]) << 4));
            unsigned bf[4][4];
#pragma unroll
            for (int bt = 0; bt < 4; ++bt)
                ldx4(bf[bt], Bb + brow[bt] + ((kc8 ^ bbit[bt]) << 4));
#pragma unroll
            for (int mt = 0; mt < 4; ++mt)
#pragma unroll
                for (int nt = 0; nt < 8; ++nt)
                    mma16816(acc[mt][nt], af[mt],
                             bf[nt >> 1][nt & 1], bf[nt >> 1][(nt & 1) + 2]);
        }
    }

    // ---- epilogue: bias add + store (f32) ----
    int r0base = m_base + wm * 64 + (lane >> 2);
    int colb   = n_base + wn * 64 + ((lane & 3) << 1);
    float2 bs[8];
#pragma unroll
    for (int nt = 0; nt < 8; ++nt)
        bs[nt] = *(const float2*)(bias + colb + nt * 8);
#pragma unroll
    for (int mt = 0; mt < 4; ++mt) {
        int r0 = r0base + mt * 16;
        int r1 = r0 + 8;
#pragma unroll
        for (int nt = 0; nt < 8; ++nt) {
            int col = colb + nt * 8;
            float2 v0 = { acc[mt][nt][0] + bs[nt].x, acc[mt][nt][1] + bs[nt].y };
            float2 v1 = { acc[mt][nt][2] + bs[nt].x, acc[mt][nt][3] + bs[nt].y };
            *(float2*)(out + (size_t)r0 * OUT_FEAT + col) = v0;
            *(float2*)(out + (size_t)r1 * OUT_FEAT + col) = v1;
        }
    }
}

// ================= launcher =================
extern "C" void kernel_launch(void* const* d_in, const int* in_sizes, int n_in,
                              void* d_out, int out_size) {
    const float* x        = (const float*)d_in[0];
    const float* base_w   = (const float*)d_in[1];
    const float* base_b   = (const float*)d_in[2];
    const float* spline_w = (const float*)d_in[3];
    float* out = (float*)d_out;

    (void)in_sizes; (void)n_in; (void)out_size;

    kan_wprep<<<OUT_FEAT, 256>>>(base_w, spline_w);
    kan_act<<<(BATCH * IN_FEAT / 2) / 256, 256>>>(x);

    cudaFuncSetAttribute(kan_gemm, cudaFuncAttributeMaxDynamicSharedMemorySize,
                         SMEM_TOTAL);
    kan_gemm<<<(BATCH / TILE_M) * (OUT_FEAT / TILE_N), 256, SMEM_TOTAL>>>(base_b, out);
}

// round 12
// speedup vs baseline: 1.7286x; 1.0340x over previous
#include <cuda_runtime.h>
#include <cuda_fp16.h>

// ---------------- problem constants ----------------
#define BATCH    8192
#define IN_FEAT  512
#define OUT_FEAT 512
#define GK       13                       // GRID_SIZE + K
#define KTOT     (IN_FEAT + IN_FEAT*GK)   // 7168
#define ROWBYTES (KTOT * 2)               // 14336 bytes per fp16 row
#define KCHUNK   64                       // fp16 elems per stage chunk = 128B
#define NCHUNKS  (KTOT / KCHUNK)          // 112
#define TILE_M   128
#define TILE_N   128
#define STAGES   3

// k-index layout is permuted (transparently to the GEMM):
//   k' in [0,512)     -> silu(x_i),            i = k'
//   k' in [512,7168)  -> basis_g(x_i),  g = (k'-512)/512, i = (k'-512)%512
// g_wk uses the identical permutation, so the dot product is unchanged.

// ---------------- scratch (device globals; no allocation allowed) ------
__device__ __half g_act[(size_t)BATCH * KTOT];     // 117 MB activation matrix
__device__ __half g_wk [(size_t)OUT_FEAT * KTOT];  // 7.3 MB packed weights

// ---------------- helpers ----------------
__device__ __forceinline__ unsigned smem_u32(const void* p) {
    unsigned a;
    asm("{ .reg .u64 t; cvta.to.shared.u64 t, %1; cvt.u32.u64 %0, t; }"
        : "=r"(a) : "l"(p));
    return a;
}
__device__ __forceinline__ void cp16(unsigned saddr, const void* gaddr) {
    asm volatile("cp.async.cg.shared.global [%0], [%1], 16;"
                 :: "r"(saddr), "l"(gaddr));
}
__device__ __forceinline__ void cp_commit() {
    asm volatile("cp.async.commit_group;");
}
template <int N>
__device__ __forceinline__ void cp_wait() {
    asm volatile("cp.async.wait_group %0;" :: "n"(N));
}
__device__ __forceinline__ void ldx4(unsigned* r, unsigned addr) {
    asm volatile("ldmatrix.sync.aligned.m8n8.x4.shared.b16 {%0,%1,%2,%3}, [%4];"
                 : "=r"(r[0]), "=r"(r[1]), "=r"(r[2]), "=r"(r[3]) : "r"(addr));
}
__device__ __forceinline__ void mma16816(float* d, const unsigned* a,
                                         unsigned b0, unsigned b1) {
    asm volatile(
        "mma.sync.aligned.m16n8k16.row.col.f32.f16.f16.f32 "
        "{%0,%1,%2,%3}, {%4,%5,%6,%7}, {%8,%9}, {%0,%1,%2,%3};"
        : "+f"(d[0]), "+f"(d[1]), "+f"(d[2]), "+f"(d[3])
        : "r"(a[0]), "r"(a[1]), "r"(a[2]), "r"(a[3]), "r"(b0), "r"(b1));
}

// ========= kernel 0: merged prep =========
// blocks [0, 512): pack one weight row o = blockIdx (permuted g-major spline)
// blocks [512, 512+8192): build one activation row b = blockIdx - 512
__global__ void __launch_bounds__(256)
kan_prep(const float* __restrict__ x,
         const float* __restrict__ base_w,
         const float* __restrict__ spline_w) {
    __shared__ __half s[IN_FEAT * 14];     // used by the weight branch only
    int tid = threadIdx.x;

    if (blockIdx.x < OUT_FEAT) {
        int o = blockIdx.x;
        const float* bw = base_w + (size_t)o * IN_FEAT;
        __half* dstb = g_wk + (size_t)o * KTOT;
#pragma unroll
        for (int i = tid; i < IN_FEAT; i += 256)
            dstb[i] = __float2half_rn(bw[i]);

        const float* sw = spline_w + (size_t)o * (IN_FEAT * GK);
        for (int idx = tid; idx < IN_FEAT * GK; idx += 256) {
            int i = idx / GK, g = idx % GK;    // coalesced read
            s[i * 14 + g] = __float2half_rn(sw[idx]);
        }
        __syncthreads();

        __half* dsts = dstb + IN_FEAT;
        for (int idx = tid; idx < IN_FEAT * GK; idx += 256) {
            int g = idx >> 9, i = idx & 511;   // k' = g*512 + i (coalesced write)
            dsts[idx] = s[i * 14 + g];
        }
        return;
    }

    // ---- activation branch: one block per batch row, thread = half2 slot ----
    int b   = blockIdx.x - OUT_FEAT;
    int ip2 = tid;                                 // 0..255
    float2 xv = *(const float2*)(x + (size_t)b * IN_FEAT + ip2 * 2);

    __half2* row2 = (__half2*)(g_act + (size_t)b * KTOT);
    float s0 = xv.x / (1.0f + __expf(-xv.x));
    float s1 = xv.y / (1.0f + __expf(-xv.y));
    row2[ip2] = __floats2half2_rn(s0, s1);

    // closed-form uniform cubic B-spline weights (knots -3.2 + 0.4j)
    float w[2][4];
    int   g0[2];
    float xs[2] = { xv.x, xv.y };
#pragma unroll
    for (int e = 0; e < 2; ++e) {
        float t = (xs[e] + 3.2f) * 2.5f;
        w[e][0] = w[e][1] = w[e][2] = w[e][3] = 0.0f;
        g0[e] = -100;
        if (t >= 0.0f && t < 16.0f) {
            int j = (int)t;
            float u  = t - (float)j;
            float um = 1.0f - u;
            float u2 = u * u, u3 = u2 * u;
            float um3 = um * um * um;
            const float c6 = 1.0f / 6.0f;
            w[e][0] = um3 * c6;
            w[e][1] = (3.0f * u3 - 6.0f * u2 + 4.0f) * c6;
            w[e][2] = (-3.0f * u3 + 3.0f * u2 + 3.0f * u + 1.0f) * c6;
            w[e][3] = u3 * c6;
            g0[e] = j - 3;
        }
    }
#pragma unroll
    for (int g = 0; g < GK; ++g) {
        int m0 = g - g0[0], m1 = g - g0[1];
        float v0 = (m0 == 0) ? w[0][0] : (m0 == 1) ? w[0][1]
                 : (m0 == 2) ? w[0][2] : (m0 == 3) ? w[0][3] : 0.0f;
        float v1 = (m1 == 0) ? w[1][0] : (m1 == 1) ? w[1][1]
                 : (m1 == 2) ? w[1][2] : (m1 == 3) ? w[1][3] : 0.0f;
        row2[256 + g * 256 + ip2] = __floats2half2_rn(v0, v1);
    }
}

// ================= kernel 1: fp16 mma.sync GEMM + bias =================
// C[8192,512] = Act[8192,7168] * Wk[512,7168]^T + bias
// CTA 128x128, 4 warps of 64x64, 3-stage cp.async ring, 2 CTAs/SM.
#define A_BYTES     (TILE_M * KCHUNK * 2)        // 16384
#define B_BYTES     (TILE_N * KCHUNK * 2)        // 16384
#define STAGE_BYTES (A_BYTES + B_BYTES)          // 32768
#define SMEM_TOTAL  (STAGES * STAGE_BYTES)       // 98304

__global__ void __launch_bounds__(128, 2)
kan_gemm(const float* __restrict__ bias, float* __restrict__ out) {
    extern __shared__ char smem[];
    unsigned sb = smem_u32(smem);
    int tid  = threadIdx.x;
    int w    = tid >> 5;
    int lane = tid & 31;
    int wm   = w >> 1;          // 0..1  (M direction, 64 rows each)
    int wn   = w & 1;           // 0..1  (N direction, 64 cols each)

    int m_base = (blockIdx.x >> 2) * TILE_M;
    int n_base = (blockIdx.x & 3) * TILE_N;

    // ---- cp.async loader precompute ----
    // 1024 16B-groups per matrix per stage; 128 threads -> 8 groups each.
    // row = (tid>>3) + q*16, c8 = tid&7; (row & 7) invariant in q.
    int  row0 = tid >> 3;                 // 0..15
    int  c8   = tid & 7;
    unsigned so = (unsigned)((row0 << 7) + (((unsigned)c8 ^ (row0 & 7)) << 4));
    const char* gA = (const char*)g_act + (size_t)(m_base + row0) * ROWBYTES + c8 * 16;
    const char* gB = (const char*)g_wk  + (size_t)(n_base + row0) * ROWBYTES + c8 * 16;

    // ---- ldmatrix per-lane precompute ----
    int lrow = lane & 15;
    unsigned lh = (unsigned)(lane >> 4);
    unsigned arow[4], abit[4], brow[4], bbit[4];
#pragma unroll
    for (int mt = 0; mt < 4; ++mt) {
        int r = wm * 64 + mt * 16 + lrow;
        arow[mt] = (unsigned)(r << 7);
        abit[mt] = (unsigned)(r & 7);
    }
#pragma unroll
    for (int bt = 0; bt < 4; ++bt) {
        int r = wn * 64 + bt * 16 + lrow;
        brow[bt] = (unsigned)(r << 7);
        bbit[bt] = (unsigned)(r & 7);
    }

    float acc[4][8][4];
#pragma unroll
    for (int mt = 0; mt < 4; ++mt)
#pragma unroll
        for (int nt = 0; nt < 8; ++nt)
#pragma unroll
            for (int e = 0; e < 4; ++e) acc[mt][nt][e] = 0.0f;

    // ---- prologue: issue chunks 0 and 1 into stages 0 and 1 ----
#pragma unroll
    for (int p = 0; p < 2; ++p) {
        unsigned base = sb + p * STAGE_BYTES;
        size_t koff = (size_t)p * 128;
#pragma unroll
        for (int q = 0; q < 8; ++q)
            cp16(base + so + q * 2048, gA + (size_t)q * 16 * ROWBYTES + koff);
#pragma unroll
        for (int q = 0; q < 8; ++q)
            cp16(base + A_BYTES + so + q * 2048, gB + (size_t)q * 16 * ROWBYTES + koff);
        cp_commit();
    }

    int s_cur = 0;   // stage of chunk c
    int s_nxt = 2;   // stage of chunk c+2 (write target)
    for (int c = 0; c < NCHUNKS; ++c) {
        if (c < NCHUNKS - 1) cp_wait<1>(); else cp_wait<0>();
        __syncthreads();   // all warps done with the stage about to be refilled

        if (c + 2 < NCHUNKS) {
            unsigned base = sb + s_nxt * STAGE_BYTES;
            size_t koff = (size_t)(c + 2) * 128;
#pragma unroll
            for (int q = 0; q < 8; ++q)
                cp16(base + so + q * 2048, gA + (size_t)q * 16 * ROWBYTES + koff);
#pragma unroll
            for (int q = 0; q < 8; ++q)
                cp16(base + A_BYTES + so + q * 2048, gB + (size_t)q * 16 * ROWBYTES + koff);
            cp_commit();
        }

        unsigned Ab = sb + s_cur * STAGE_BYTES;
        unsigned Bb = Ab + A_BYTES;
#pragma unroll
        for (int kt = 0; kt < 4; ++kt) {
            unsigned kc8 = (unsigned)(kt * 2) + lh;
            unsigned af[4][4];
#pragma unroll
            for (int mt = 0; mt < 4; ++mt)
                ldx4(af[mt], Ab + arow[mt] + ((kc8 ^ abit[mt]) << 4));
            unsigned bf[4][4];
#pragma unroll
            for (int bt = 0; bt < 4; ++bt)
                ldx4(bf[bt], Bb + brow[bt] + ((kc8 ^ bbit[bt]) << 4));
#pragma unroll
            for (int mt = 0; mt < 4; ++mt)
#pragma unroll
                for (int nt = 0; nt < 8; ++nt)
                    mma16816(acc[mt][nt], af[mt],
                             bf[nt >> 1][nt & 1], bf[nt >> 1][(nt & 1) + 2]);
        }

        s_cur = (s_cur == STAGES - 1) ? 0 : s_cur + 1;
        s_nxt = (s_nxt == STAGES - 1) ? 0 : s_nxt + 1;
    }

    // ---- epilogue: bias add + store (f32) ----
    int r0base = m_base + wm * 64 + (lane >> 2);
    int colb   = n_base + wn * 64 + ((lane & 3) << 1);
    float2 bs[8];
#pragma unroll
    for (int nt = 0; nt < 8; ++nt)
        bs[nt] = *(const float2*)(bias + colb + nt * 8);
#pragma unroll
    for (int mt = 0; mt < 4; ++mt) {
        int r0 = r0base + mt * 16;
        int r1 = r0 + 8;
#pragma unroll
        for (int nt = 0; nt < 8; ++nt) {
            int col = colb + nt * 8;
            float2 v0 = { acc[mt][nt][0] + bs[nt].x, acc[mt][nt][1] + bs[nt].y };
            float2 v1 = { acc[mt][nt][2] + bs[nt].x, acc[mt][nt][3] + bs[nt].y };
            *(float2*)(out + (size_t)r0 * OUT_FEAT + col) = v0;
            *(float2*)(out + (size_t)r1 * OUT_FEAT + col) = v1;
        }
    }
}

// ================= launcher =================
extern "C" void kernel_launch(void* const* d_in, const int* in_sizes, int n_in,
                              void* d_out, int out_size) {
    const float* x        = (const float*)d_in[0];
    const float* base_w   = (const float*)d_in[1];
    const float* base_b   = (const float*)d_in[2];
    const float* spline_w = (const float*)d_in[3];
    float* out = (float*)d_out;

    (void)in_sizes; (void)n_in; (void)out_size;

    kan_prep<<<OUT_FEAT + BATCH, 256>>>(x, base_w, spline_w);

    cudaFuncSetAttribute(kan_gemm, cudaFuncAttributeMaxDynamicSharedMemorySize,
                         SMEM_TOTAL);
    kan_gemm<<<(BATCH / TILE_M) * (OUT_FEAT / TILE_N), 128, SMEM_TOTAL>>>(base_b, out);
}

// round 14
// speedup vs baseline: 1.9398x; 1.1222x over previous
#include <cuda_runtime.h>
#include <cuda_fp16.h>

// ---------------- problem constants ----------------
#define BATCH    8192
#define IN_FEAT  512
#define OUT_FEAT 512
#define GK       13                       // GRID_SIZE + K
#define KTOT     (IN_FEAT + IN_FEAT*GK)   // 7168
#define ROWBYTES (KTOT * 2)               // 14336 bytes per fp16 row
#define KCHUNK   64                       // fp16 elems per stage chunk = 128B
#define NCHUNKS  (KTOT / KCHUNK)          // 112
#define TILE_M   128
#define TILE_N   64
#define STAGES   2

// k' layout (permuted, transparent to the GEMM):
//   k' in [0,512)     -> silu(x_i),           i = k'
//   k' in [512,7168)  -> basis_g(x_i), g = (k'-512)/512, i = (k'-512)%512
// g_wk uses the identical permutation, so the dot product is unchanged.

// ---------------- scratch (device globals; no allocation allowed) ------
__device__ __half g_act[(size_t)BATCH * KTOT];     // 117 MB activation matrix
__device__ __half g_wk [(size_t)OUT_FEAT * KTOT];  // 7.3 MB packed weights

// ---------------- helpers ----------------
__device__ __forceinline__ unsigned smem_u32(const void* p) {
    unsigned a;
    asm("{ .reg .u64 t; cvta.to.shared.u64 t, %1; cvt.u32.u64 %0, t; }"
        : "=r"(a) : "l"(p));
    return a;
}
__device__ __forceinline__ void cp16(unsigned saddr, const void* gaddr) {
    asm volatile("cp.async.cg.shared.global [%0], [%1], 16;"
                 :: "r"(saddr), "l"(gaddr));
}
__device__ __forceinline__ void cp_commit() {
    asm volatile("cp.async.commit_group;");
}
template <int N>
__device__ __forceinline__ void cp_wait() {
    asm volatile("cp.async.wait_group %0;" :: "n"(N));
}
__device__ __forceinline__ void ldx4(unsigned* r, unsigned addr) {
    asm volatile("ldmatrix.sync.aligned.m8n8.x4.shared.b16 {%0,%1,%2,%3}, [%4];"
                 : "=r"(r[0]), "=r"(r[1]), "=r"(r[2]), "=r"(r[3]) : "r"(addr));
}
__device__ __forceinline__ void mma16816(float* d, const unsigned* a,
                                         unsigned b0, unsigned b1) {
    asm volatile(
        "mma.sync.aligned.m16n8k16.row.col.f32.f16.f16.f32 "
        "{%0,%1,%2,%3}, {%4,%5,%6,%7}, {%8,%9}, {%0,%1,%2,%3};"
        : "+f"(d[0]), "+f"(d[1]), "+f"(d[2]), "+f"(d[3])
        : "r"(a[0]), "r"(a[1]), "r"(a[2]), "r"(a[3]), "r"(b0), "r"(b1));
}

// ========= kernel 0: merged prep =========
// blocks [0, 512): pack one weight row o (permuted g-major spline)
// blocks [512, 512 + 4096): build TWO activation rows via smem scatter
__global__ void __launch_bounds__(256)
kan_prep(const float* __restrict__ x,
         const float* __restrict__ base_w,
         const float* __restrict__ spline_w) {
    __shared__ __half s[2 * KTOT];         // 28672 B
    int tid = threadIdx.x;

    if (blockIdx.x < OUT_FEAT) {
        // ---- weight branch: transpose spline row to g-major ----
        int o = blockIdx.x;
        const float* bw = base_w + (size_t)o * IN_FEAT;
        __half* dstb = g_wk + (size_t)o * KTOT;
#pragma unroll
        for (int i = tid; i < IN_FEAT; i += 256)
            dstb[i] = __float2half_rn(bw[i]);

        const float* sw = spline_w + (size_t)o * (IN_FEAT * GK);
        for (int idx = tid; idx < IN_FEAT * GK; idx += 256) {
            int i = idx / GK, g = idx % GK;    // coalesced read
            s[i * 14 + g] = __float2half_rn(sw[idx]);
        }
        __syncthreads();

        __half* dsts = dstb + IN_FEAT;
        for (int idx = tid; idx < IN_FEAT * GK; idx += 256) {
            int g = idx >> 9, i = idx & 511;   // k' = g*512 + i (coalesced write)
            dsts[idx] = s[i * 14 + g];
        }
        return;
    }

    // ---- activation branch: 2 rows per block, scatter nonzero bases ----
    int r0 = (blockIdx.x - OUT_FEAT) * 2;

    // phase 1: zero the 28 KB row image
    int4* z = (int4*)s;
#pragma unroll
    for (int k = 0; k < 7; ++k)
        z[tid + k * 256] = make_int4(0, 0, 0, 0);
    __syncthreads();

    // phase 2: each thread computes 4 consecutive x elems of one row
    int row = tid >> 7;                    // 0..1
    int i0  = (tid & 127) << 2;            // 0..508
    float4 xv = *(const float4*)(x + (size_t)(r0 + row) * IN_FEAT + i0);
    __half* srow = s + row * KTOT;
    float xs[4] = { xv.x, xv.y, xv.z, xv.w };
#pragma unroll
    for (int e = 0; e < 4; ++e) {
        float v = xs[e];
        srow[i0 + e] = __float2half_rn(v / (1.0f + __expf(-v)));   // silu
        float t = (v + 3.2f) * 2.5f;       // knots -3.2 + 0.4j
        if (t >= 0.0f && t < 16.0f) {
            int j = (int)t;
            float u  = t - (float)j;
            float um = 1.0f - u;
            float u2 = u * u, u3 = u2 * u;
            float um3 = um * um * um;
            const float c6 = 1.0f / 6.0f;
            float wv[4];
            wv[0] = um3 * c6;
            wv[1] = (3.0f * u3 - 6.0f * u2 + 4.0f) * c6;
            wv[2] = (-3.0f * u3 + 3.0f * u2 + 3.0f * u + 1.0f) * c6;
            wv[3] = u3 * c6;
            int g0 = j - 3;
#pragma unroll
            for (int d = 0; d < 4; ++d) {
                int g = g0 + d;
                if (g >= 0 && g < GK)      // reference truncates edge bases
                    srow[IN_FEAT + (g << 9) + i0 + e] = __float2half_rn(wv[d]);
            }
        }
    }
    __syncthreads();

    // phase 3: coalesced copy-out (rows r0, r0+1 are contiguous in g_act)
    const int4* src = (const int4*)s;
    int4* dst = (int4*)(g_act + (size_t)r0 * KTOT);
#pragma unroll
    for (int k = 0; k < 7; ++k)
        dst[tid + k * 256] = src[tid + k * 256];
}

// ================= kernel 1: fp16 mma.sync GEMM + bias =================
// C[8192,512] = Act[8192,7168] * Wk[512,7168]^T + bias
// CTA 128x64, 4 warps of 64x32, 2-stage cp.async ring, 4 CTAs/SM.
#define A_BYTES     (TILE_M * KCHUNK * 2)        // 16384
#define B_BYTES     (TILE_N * KCHUNK * 2)        // 8192
#define STAGE_BYTES (A_BYTES + B_BYTES)          // 24576
#define SMEM_TOTAL  (STAGES * STAGE_BYTES)       // 49152

__global__ void __launch_bounds__(128, 4)
kan_gemm(const float* __restrict__ bias, float* __restrict__ out) {
    extern __shared__ char smem[];
    unsigned sb = smem_u32(smem);
    int tid  = threadIdx.x;
    int w    = tid >> 5;
    int lane = tid & 31;
    int wm   = w >> 1;          // 0..1  (M direction, 64 rows each)
    int wn   = w & 1;           // 0..1  (N direction, 32 cols each)

    int m_base = (blockIdx.x >> 3) * TILE_M;
    int n_base = (blockIdx.x & 7) * TILE_N;

    // ---- cp.async loader precompute ----
    // A: 1024 16B groups -> 8 per thread; B: 512 groups -> 4 per thread.
    // row = (tid>>3) + q*16, c8 = tid&7; (row & 7) invariant in q.
    int  row0 = tid >> 3;                 // 0..15
    int  c8   = tid & 7;
    unsigned so = (unsigned)((row0 << 7) + (((unsigned)c8 ^ (row0 & 7)) << 4));
    const char* gA = (const char*)g_act + (size_t)(m_base + row0) * ROWBYTES + c8 * 16;
    const char* gB = (const char*)g_wk  + (size_t)(n_base + row0) * ROWBYTES + c8 * 16;

    // ---- ldmatrix per-lane precompute ----
    int lrow = lane & 15;
    unsigned lh = (unsigned)(lane >> 4);
    unsigned arow[4], abit[4], brow[2], bbit[2];
#pragma unroll
    for (int mt = 0; mt < 4; ++mt) {
        int r = wm * 64 + mt * 16 + lrow;
        arow[mt] = (unsigned)(r << 7);
        abit[mt] = (unsigned)(r & 7);
    }
#pragma unroll
    for (int bt = 0; bt < 2; ++bt) {
        int r = wn * 32 + bt * 16 + lrow;
        brow[bt] = (unsigned)(r << 7);
        bbit[bt] = (unsigned)(r & 7);
    }

    float acc[4][4][4];
#pragma unroll
    for (int mt = 0; mt < 4; ++mt)
#pragma unroll
        for (int nt = 0; nt < 4; ++nt)
#pragma unroll
            for (int e = 0; e < 4; ++e) acc[mt][nt][e] = 0.0f;

    // ---- prologue: issue chunk 0 into stage 0 ----
#pragma unroll
    for (int q = 0; q < 8; ++q)
        cp16(sb + so + q * 2048, gA + (size_t)q * 16 * ROWBYTES);
#pragma unroll
    for (int q = 0; q < 4; ++q)
        cp16(sb + A_BYTES + so + q * 2048, gB + (size_t)q * 16 * ROWBYTES);
    cp_commit();

    for (int c = 0; c < NCHUNKS; ++c) {
        cp_wait<0>();          // chunk c has landed
        __syncthreads();       // all warps done with the stage being refilled

        if (c + 1 < NCHUNKS) {
            unsigned base = sb + ((c + 1) & 1) * STAGE_BYTES;
            size_t koff = (size_t)(c + 1) * 128;
#pragma unroll
            for (int q = 0; q < 8; ++q)
                cp16(base + so + q * 2048, gA + (size_t)q * 16 * ROWBYTES + koff);
#pragma unroll
            for (int q = 0; q < 4; ++q)
                cp16(base + A_BYTES + so + q * 2048, gB + (size_t)q * 16 * ROWBYTES + koff);
            cp_commit();
        }

        unsigned Ab = sb + (c & 1) * STAGE_BYTES;
        unsigned Bb = Ab + A_BYTES;
#pragma unroll
        for (int kt = 0; kt < 4; ++kt) {
            unsigned kc8 = (unsigned)(kt * 2) + lh;
            unsigned af[4][4];
#pragma unroll
            for (int mt = 0; mt < 4; ++mt)
                ldx4(af[mt], Ab + arow[mt] + ((kc8 ^ abit[mt]) << 4));
            unsigned bf[2][4];
#pragma unroll
            for (int bt = 0; bt < 2; ++bt)
                ldx4(bf[bt], Bb + brow[bt] + ((kc8 ^ bbit[bt]) << 4));
#pragma unroll
            for (int mt = 0; mt < 4; ++mt)
#pragma unroll
                for (int nt = 0; nt < 4; ++nt)
                    mma16816(acc[mt][nt], af[mt],
                             bf[nt >> 1][nt & 1], bf[nt >> 1][(nt & 1) + 2]);
        }
    }

    // ---- epilogue: bias add + store (f32) ----
    int r0base = m_base + wm * 64 + (lane >> 2);
    int colb   = n_base + wn * 32 + ((lane & 3) << 1);
    float2 bs[4];
#pragma unroll
    for (int nt = 0; nt < 4; ++nt)
        bs[nt] = *(const float2*)(bias + colb + nt * 8);
#pragma unroll
    for (int mt = 0; mt < 4; ++mt) {
        int r0 = r0base + mt * 16;
        int r1 = r0 + 8;
#pragma unroll
        for (int nt = 0; nt < 4; ++nt) {
            int col = colb + nt * 8;
            float2 v0 = { acc[mt][nt][0] + bs[nt].x, acc[mt][nt][1] + bs[nt].y };
            float2 v1 = { acc[mt][nt][2] + bs[nt].x, acc[mt][nt][3] + bs[nt].y };
            *(float2*)(out + (size_t)r0 * OUT_FEAT + col) = v0;
            *(float2*)(out + (size_t)r1 * OUT_FEAT + col) = v1;
        }
    }
}

// ================= launcher =================
extern "C" void kernel_launch(void* const* d_in, const int* in_sizes, int n_in,
                              void* d_out, int out_size) {
    const float* x        = (const float*)d_in[0];
    const float* base_w   = (const float*)d_in[1];
    const float* base_b   = (const float*)d_in[2];
    const float* spline_w = (const float*)d_in[3];
    float* out = (float*)d_out;

    (void)in_sizes; (void)n_in; (void)out_size;

    kan_prep<<<OUT_FEAT + BATCH / 2, 256>>>(x, base_w, spline_w);

    cudaFuncSetAttribute(kan_gemm, cudaFuncAttributeMaxDynamicSharedMemorySize,
                         SMEM_TOTAL);
    kan_gemm<<<(BATCH / TILE_M) * (OUT_FEAT / TILE_N), 128, SMEM_TOTAL>>>(base_b, out);
}